// round 4
// baseline (speedup 1.0000x reference)
#include <cuda_runtime.h>
#include <math.h>
#include <float.h>

#define NN 50000
#define NE 500000
#define DD 64
#define NLAYERS 4
#define INV_N (1.0f/50000.0f)
#define INV_SQRT_N 0.004472135954999579f

// ---------------- scratch (static device allocations; no cudaMalloc) ----------------
__device__ float g_AB[NN * 128];     // [A | B+bM] per node
__device__ float g_AGG[NN * 384];    // [mean,max,min,std,var,sum] x 64
__device__ float g_HU[NN * 64];
__device__ float g_OUT[NN * 64];
__device__ float g_HA[NN * 64];
__device__ float g_HB[NN * 64];
__device__ int   g_degi[NN];
__device__ int   g_off[NN + 1];
__device__ int   g_cursor[NN];
__device__ int   g_csr[NE];
__device__ float g_amp[NN];
__device__ float g_att[NN];
__device__ float g_stats[128];       // colsum[64], colsumsq[64]
__device__ float g_Wp[64 * 64];      // BN-folded Wmix
__device__ float g_dp[64];           // BN-folded bias

// ---------------- CSR build ----------------
__global__ void k_zero_degi() {
    int i = blockIdx.x * blockDim.x + threadIdx.x;
    if (i < NN) g_degi[i] = 0;
}

__global__ void k_hist(const int* __restrict__ dst) {
    int e = blockIdx.x * blockDim.x + threadIdx.x;
    if (e < NE) atomicAdd(&g_degi[dst[e]], 1);
}

__global__ void k_scan() {   // single block, 1024 threads: exclusive scan of g_degi -> g_off
    __shared__ int carry;
    __shared__ int warp_sums[32];
    int tid = threadIdx.x;
    if (tid == 0) carry = 0;
    __syncthreads();
    for (int base = 0; base < NN; base += 1024) {
        int i = base + tid;
        int v = (i < NN) ? g_degi[i] : 0;
        int incl = v;
        #pragma unroll
        for (int o = 1; o < 32; o <<= 1) {
            int t = __shfl_up_sync(0xffffffffu, incl, o);
            if ((tid & 31) >= o) incl += t;
        }
        if ((tid & 31) == 31) warp_sums[tid >> 5] = incl;
        __syncthreads();
        if (tid < 32) {
            int s = warp_sums[tid];
            #pragma unroll
            for (int o = 1; o < 32; o <<= 1) {
                int t = __shfl_up_sync(0xffffffffu, s, o);
                if (tid >= o) s += t;
            }
            warp_sums[tid] = s;
        }
        __syncthreads();
        int excl = incl - v + ((tid >= 32) ? warp_sums[(tid >> 5) - 1] : 0);
        if (i < NN) g_off[i] = carry + excl;
        __syncthreads();
        if (tid == 1023) carry += excl + v;
        __syncthreads();
    }
    if (tid == 0) g_off[NN] = NE;
}

__global__ void k_copy_cursor() {
    int i = blockIdx.x * blockDim.x + threadIdx.x;
    if (i < NN) g_cursor[i] = g_off[i];
}

__global__ void k_scatter(const int* __restrict__ src, const int* __restrict__ dst) {
    int e = blockIdx.x * blockDim.x + threadIdx.x;
    if (e < NE) {
        int d = dst[e];
        int p = atomicAdd(&g_cursor[d], 1);
        g_csr[p] = src[e];
    }
}

__global__ void k_degscale() {
    int i = blockIdx.x * blockDim.x + threadIdx.x;
    if (i < NN) {
        int d = g_off[i + 1] - g_off[i];
        float logD = logf((float)d + 1.0f);
        g_amp[i] = logD / 2.5f;
        g_att[i] = (d > 0) ? 2.5f / logD : 0.0f;
    }
}

// ---------------- generic 64-col FP32 GEMM: C[M x 64] = X[M x K] @ W[K x 64] ----------------
// mode 0: C = acc + bias
// mode 1: C = leaky_relu(acc + bias, 0.01) + resid     (PNAConv internal residual)
__global__ __launch_bounds__(256) void gemm64(
    const float* __restrict__ X, int ldx,
    const float* __restrict__ W,             // K x 64 row-major
    const float* __restrict__ bias,
    float* __restrict__ C, int ldc,
    int K, int mode, const float* __restrict__ resid)
{
    __shared__ float Xs[16][68];
    __shared__ float Ws[16][64];
    int tid = threadIdx.x;
    int tx = tid & 15, ty = tid >> 4;
    int row0 = blockIdx.y * 64;
    float acc[4][4] = {};

    int lrow = tid >> 2;          // 0..63
    int lk   = (tid & 3) * 4;     // 0,4,8,12
    int wk   = tid >> 4;          // 0..15
    int wc   = (tid & 15) * 4;

    for (int kt = 0; kt < K; kt += 16) {
        int grow = row0 + lrow;
        float4 xv = make_float4(0.f, 0.f, 0.f, 0.f);
        if (grow < NN) xv = *(const float4*)&X[(size_t)grow * ldx + kt + lk];
        Xs[lk + 0][lrow] = xv.x; Xs[lk + 1][lrow] = xv.y;
        Xs[lk + 2][lrow] = xv.z; Xs[lk + 3][lrow] = xv.w;
        *(float4*)&Ws[wk][wc] = *(const float4*)&W[(size_t)(kt + wk) * 64 + wc];
        __syncthreads();
        #pragma unroll
        for (int kk = 0; kk < 16; kk++) {
            float4 a = *(const float4*)&Xs[kk][ty * 4];
            float4 b = *(const float4*)&Ws[kk][tx * 4];
            float av[4] = {a.x, a.y, a.z, a.w};
            float bv[4] = {b.x, b.y, b.z, b.w};
            #pragma unroll
            for (int i = 0; i < 4; i++)
                #pragma unroll
                for (int j = 0; j < 4; j++)
                    acc[i][j] += av[i] * bv[j];
        }
        __syncthreads();
    }
    #pragma unroll
    for (int i = 0; i < 4; i++) {
        int r = row0 + ty * 4 + i;
        if (r < NN) {
            #pragma unroll
            for (int j = 0; j < 4; j++) {
                int c = tx * 4 + j;
                float v = acc[i][j] + (bias ? bias[c] : 0.0f);
                if (mode == 1) {
                    v = (v > 0.0f) ? v : 0.01f * v;
                    v += resid[(size_t)r * 64 + c];
                }
                C[(size_t)r * ldc + c] = v;
            }
        }
    }
}

// ---------------- per-node aggregation: reduces A[src] over incoming edges ----------------
__global__ __launch_bounds__(256) void k_agg() {
    int node = blockIdx.x * (blockDim.x >> 5) + (threadIdx.x >> 5);
    if (node >= NN) return;
    int lane = threadIdx.x & 31;
    int beg = g_off[node], end = g_off[node + 1];

    float sx = 0.f, sy = 0.f, qx = 0.f, qy = 0.f;
    float mxx = -FLT_MAX, mxy = -FLT_MAX, mnx = FLT_MAX, mny = FLT_MAX;
    for (int e = beg; e < end; e++) {
        int s = g_csr[e];
        float2 a = *(const float2*)&g_AB[(size_t)s * 128 + 2 * lane];
        sx += a.x; sy += a.y;
        qx += a.x * a.x; qy += a.y * a.y;
        mxx = fmaxf(mxx, a.x); mxy = fmaxf(mxy, a.y);
        mnx = fminf(mnx, a.x); mny = fminf(mny, a.y);
    }
    float degf = (float)(end - beg);
    float denom = fmaxf(degf, 1.0f);
    float2 Bd = *(const float2*)&g_AB[(size_t)node * 128 + 64 + 2 * lane];

    // reconstruct aggregates of msg = A[src] + Bd
    float sumx = sx + degf * Bd.x;
    float sumy = sy + degf * Bd.y;
    float meanx = sumx / denom, meany = sumy / denom;
    float msqx = (qx + 2.f * Bd.x * sx + degf * Bd.x * Bd.x) / denom;
    float msqy = (qy + 2.f * Bd.y * sy + degf * Bd.y * Bd.y) / denom;
    float varx = fmaxf(msqx - meanx * meanx, 0.f);
    float vary = fmaxf(msqy - meany * meany, 0.f);
    float stdx = sqrtf(varx + 1e-30f);
    float stdy = sqrtf(vary + 1e-30f);
    bool has = degf > 0.f;
    float Mx = has ? mxx + Bd.x : 0.f, My = has ? mxy + Bd.y : 0.f;
    float mx_ = has ? mnx + Bd.x : 0.f, my_ = has ? mny + Bd.y : 0.f;

    size_t base = (size_t)node * 384 + 2 * lane;
    *(float2*)&g_AGG[base + 0 * 64] = make_float2(meanx, meany);
    *(float2*)&g_AGG[base + 1 * 64] = make_float2(Mx, My);
    *(float2*)&g_AGG[base + 2 * 64] = make_float2(mx_, my_);
    *(float2*)&g_AGG[base + 3 * 64] = make_float2(stdx, stdy);
    *(float2*)&g_AGG[base + 4 * 64] = make_float2(varx, vary);
    *(float2*)&g_AGG[base + 5 * 64] = make_float2(sumx, sumy);
}

// ---------------- fused update GEMM: hu = (H@WU0 + AGG@Wid + amp*(AGG@Wamp) + att*(AGG@Watt) + bU)/sqrt(N) ----------------
__global__ __launch_bounds__(256) void gemm_hu(
    const float* __restrict__ H,
    const float* __restrict__ WU,   // 1216 x 64 (layer slice)
    const float* __restrict__ bU)
{
    __shared__ float Xs[16][68];
    __shared__ float W0s[16][64];
    __shared__ float W1s[16][64];
    __shared__ float W2s[16][64];
    int tid = threadIdx.x;
    int tx = tid & 15, ty = tid >> 4;
    int row0 = blockIdx.y * 64;
    float aid[4][4] = {}, aam[4][4] = {}, aat[4][4] = {};

    int lrow = tid >> 2;
    int lk   = (tid & 3) * 4;
    int wk   = tid >> 4;
    int wc   = (tid & 15) * 4;

    // phase 1: self features, K = 64, WU rows [0,64)
    for (int kt = 0; kt < 64; kt += 16) {
        int grow = row0 + lrow;
        float4 xv = make_float4(0.f, 0.f, 0.f, 0.f);
        if (grow < NN) xv = *(const float4*)&H[(size_t)grow * 64 + kt + lk];
        Xs[lk + 0][lrow] = xv.x; Xs[lk + 1][lrow] = xv.y;
        Xs[lk + 2][lrow] = xv.z; Xs[lk + 3][lrow] = xv.w;
        *(float4*)&W0s[wk][wc] = *(const float4*)&WU[(size_t)(kt + wk) * 64 + wc];
        __syncthreads();
        #pragma unroll
        for (int kk = 0; kk < 16; kk++) {
            float4 a = *(const float4*)&Xs[kk][ty * 4];
            float4 b = *(const float4*)&W0s[kk][tx * 4];
            float av[4] = {a.x, a.y, a.z, a.w};
            float bv[4] = {b.x, b.y, b.z, b.w};
            #pragma unroll
            for (int i = 0; i < 4; i++)
                #pragma unroll
                for (int j = 0; j < 4; j++)
                    aid[i][j] += av[i] * bv[j];
        }
        __syncthreads();
    }
    // phase 2: aggregates, K = 384, three weight streams (id/amp/att)
    for (int kt = 0; kt < 384; kt += 16) {
        int grow = row0 + lrow;
        float4 xv = make_float4(0.f, 0.f, 0.f, 0.f);
        if (grow < NN) xv = *(const float4*)&g_AGG[(size_t)grow * 384 + kt + lk];
        Xs[lk + 0][lrow] = xv.x; Xs[lk + 1][lrow] = xv.y;
        Xs[lk + 2][lrow] = xv.z; Xs[lk + 3][lrow] = xv.w;
        *(float4*)&W0s[wk][wc] = *(const float4*)&WU[(size_t)(64  + kt + wk) * 64 + wc];
        *(float4*)&W1s[wk][wc] = *(const float4*)&WU[(size_t)(448 + kt + wk) * 64 + wc];
        *(float4*)&W2s[wk][wc] = *(const float4*)&WU[(size_t)(832 + kt + wk) * 64 + wc];
        __syncthreads();
        #pragma unroll
        for (int kk = 0; kk < 16; kk++) {
            float4 a  = *(const float4*)&Xs[kk][ty * 4];
            float4 b0 = *(const float4*)&W0s[kk][tx * 4];
            float4 b1 = *(const float4*)&W1s[kk][tx * 4];
            float4 b2 = *(const float4*)&W2s[kk][tx * 4];
            float av[4]  = {a.x, a.y, a.z, a.w};
            float b0v[4] = {b0.x, b0.y, b0.z, b0.w};
            float b1v[4] = {b1.x, b1.y, b1.z, b1.w};
            float b2v[4] = {b2.x, b2.y, b2.z, b2.w};
            #pragma unroll
            for (int i = 0; i < 4; i++)
                #pragma unroll
                for (int j = 0; j < 4; j++) {
                    aid[i][j] += av[i] * b0v[j];
                    aam[i][j] += av[i] * b1v[j];
                    aat[i][j] += av[i] * b2v[j];
                }
        }
        __syncthreads();
    }
    #pragma unroll
    for (int i = 0; i < 4; i++) {
        int r = row0 + ty * 4 + i;
        if (r < NN) {
            float amp = g_amp[r], att = g_att[r];
            #pragma unroll
            for (int j = 0; j < 4; j++) {
                int c = tx * 4 + j;
                float v = aid[i][j] + amp * aam[i][j] + att * aat[i][j] + bU[c];
                g_HU[(size_t)r * 64 + c] = v * INV_SQRT_N;
            }
        }
    }
}

// ---------------- batchnorm stats ----------------
__global__ void k_zero_stats() {
    if (threadIdx.x < 128) g_stats[threadIdx.x] = 0.f;
}

__global__ __launch_bounds__(256) void bn_stats(const float* __restrict__ X) {
    __shared__ float ssum[64], ssq[64];
    int tid = threadIdx.x;
    if (tid < 64) { ssum[tid] = 0.f; ssq[tid] = 0.f; }
    __syncthreads();
    int c = tid & 63;
    int r0 = blockIdx.x * 4 + (tid >> 6);
    float s = 0.f, q = 0.f;
    for (int row = r0; row < NN; row += gridDim.x * 4) {
        float v = X[(size_t)row * 64 + c];
        s += v; q += v * v;
    }
    atomicAdd(&ssum[c], s);
    atomicAdd(&ssq[c], q);
    __syncthreads();
    if (tid < 64) {
        atomicAdd(&g_stats[tid], ssum[tid]);
        atomicAdd(&g_stats[64 + tid], ssq[tid]);
    }
}

// fold tower BN into Wmix:  hbn@Wmix + bmix  ==  hu@Wp + dp
__global__ void prep_mix(const float* __restrict__ Wmix, const float* __restrict__ bmix,
                         const float* __restrict__ gt, const float* __restrict__ bt) {
    __shared__ float a[64], cc[64];
    int tid = threadIdx.x;
    if (tid < 64) {
        float mu = g_stats[tid] * INV_N;
        float var = g_stats[64 + tid] * INV_N - mu * mu;
        float rstd = rsqrtf(var + 1e-5f);
        float aa = rstd * gt[tid];
        a[tid] = aa;
        cc[tid] = bt[tid] - mu * aa;
    }
    __syncthreads();
    for (int idx = tid; idx < 4096; idx += blockDim.x) {
        int k = idx >> 6;
        g_Wp[idx] = a[k] * Wmix[idx];
    }
    if (tid < 64) {
        float d = bmix[tid];
        for (int k = 0; k < 64; k++) d += cc[k] * Wmix[k * 64 + tid];
        g_dp[tid] = d;
    }
}

// outer wrapper: h_next = relu(bn_o(out)) + h
__global__ __launch_bounds__(256) void k_apply(const float* __restrict__ go, const float* __restrict__ bo,
                                               const float* __restrict__ Hin, float* __restrict__ Hout) {
    int idx = blockIdx.x * blockDim.x + threadIdx.x;
    if (idx >= NN * 64) return;
    int c = idx & 63;
    float mu = g_stats[c] * INV_N;
    float var = g_stats[64 + c] * INV_N - mu * mu;
    float rstd = rsqrtf(var + 1e-5f);
    float v = (g_OUT[idx] - mu) * rstd * go[c] + bo[c];
    v = fmaxf(v, 0.f);
    Hout[idx] = v + Hin[idx];
}

// ---------------- host ----------------
extern "C" void kernel_launch(void* const* d_in, const int* in_sizes, int n_in,
                              void* d_out, int out_size) {
    const float* node_feat = (const float*)d_in[0];
    const int*   esrc      = (const int*)d_in[2];
    const int*   edst      = (const int*)d_in[3];
    const float* WM        = (const float*)d_in[4];
    const float* bM        = (const float*)d_in[5];
    const float* WU        = (const float*)d_in[6];
    const float* bU        = (const float*)d_in[7];
    const float* gt        = (const float*)d_in[8];
    const float* bt        = (const float*)d_in[9];
    const float* Wmix      = (const float*)d_in[10];
    const float* bmix      = (const float*)d_in[11];
    const float* go        = (const float*)d_in[12];
    const float* bo        = (const float*)d_in[13];
    float* out = (float*)d_out;

    float *pAB, *pHU, *pOUT, *pHA, *pHB, *pWp, *pdp;
    cudaGetSymbolAddress((void**)&pAB,  g_AB);
    cudaGetSymbolAddress((void**)&pHU,  g_HU);
    cudaGetSymbolAddress((void**)&pOUT, g_OUT);
    cudaGetSymbolAddress((void**)&pHA,  g_HA);
    cudaGetSymbolAddress((void**)&pHB,  g_HB);
    cudaGetSymbolAddress((void**)&pWp,  g_Wp);
    cudaGetSymbolAddress((void**)&pdp,  g_dp);

    // CSR build (graph static across layers)
    k_zero_degi<<<(NN + 255) / 256, 256>>>();
    k_hist<<<(NE + 255) / 256, 256>>>(edst);
    k_scan<<<1, 1024>>>();
    k_copy_cursor<<<(NN + 255) / 256, 256>>>();
    k_scatter<<<(NE + 255) / 256, 256>>>(esrc, edst);
    k_degscale<<<(NN + 255) / 256, 256>>>();

    dim3 ggrid(1, (NN + 63) / 64);
    for (int l = 0; l < NLAYERS; l++) {
        const float* Hin  = (l == 0) ? node_feat : ((l & 1) ? pHA : pHB);
        float*       Hout = (l == 3) ? out       : ((l & 1) ? pHB : pHA);
        const float* WMl  = WM + (size_t)l * 128 * 64;
        const float* WUl  = WU + (size_t)l * 1216 * 64;

        // A = H@WM_top ; B = H@WM_bot + bM   (interleaved into g_AB rows of 128)
        gemm64<<<ggrid, 256>>>(Hin, 64, WMl,           nullptr,      pAB,      128, 64, 0, nullptr);
        gemm64<<<ggrid, 256>>>(Hin, 64, WMl + 64 * 64, bM + l * 64,  pAB + 64, 128, 64, 0, nullptr);

        k_agg<<<(NN + 7) / 8, 256>>>();

        gemm_hu<<<ggrid, 256>>>(Hin, WUl, bU + l * 64);

        k_zero_stats<<<1, 128>>>();
        bn_stats<<<256, 256>>>(pHU);
        prep_mix<<<1, 256>>>(Wmix + (size_t)l * 4096, bmix + l * 64, gt + l * 64, bt + l * 64);

        // out = leaky_relu(hu@Wp + dp) + Hin
        gemm64<<<ggrid, 256>>>(pHU, 64, pWp, pdp, pOUT, 64, 64, 1, Hin);

        k_zero_stats<<<1, 128>>>();
        bn_stats<<<256, 256>>>(pOUT);
        k_apply<<<(NN * 64 + 255) / 256, 256>>>(go + l * 64, bo + l * 64, Hin, Hout);
    }
}

// round 5
// speedup vs baseline: 1.0879x; 1.0879x over previous
#include <cuda_runtime.h>
#include <math.h>
#include <float.h>

#define NN 50000
#define NE 500000
#define NLAYERS 4
#define INV_N (1.0f/50000.0f)
#define INV_SQRT_N 0.004472135954999579f

typedef unsigned long long u64;

// ---------------- scratch ----------------
__device__ float g_AB[NN * 128];     // [A | B+bM] per node
__device__ float g_AGG[NN * 384];    // [mean,max,min,std,var,sum] x 64
__device__ float g_HU[NN * 64];
__device__ float g_OUT[NN * 64];
__device__ float g_HA[NN * 64];
__device__ float g_HB[NN * 64];
__device__ int   g_degi[NN];
__device__ int   g_off[NN + 1];
__device__ int   g_cursor[NN];
__device__ int   g_csr[NE];
__device__ float g_amp[NN];
__device__ float g_att[NN];
__device__ float g_stats[128];       // HU:  colsum[64], colsumsq[64]
__device__ float g_stats2[128];      // OUT: colsum[64], colsumsq[64]
__device__ float g_Wp[64 * 64];      // BN-folded Wmix
__device__ float g_dp[64];           // BN-folded bias

// ---------------- f32x2 / cp.async helpers ----------------
__device__ __forceinline__ void ffma2(u64& d, u64 a, u64 b) {
    asm("fma.rn.f32x2 %0, %1, %2, %0;" : "+l"(d) : "l"(a), "l"(b));
}
__device__ __forceinline__ u64 pack2(float x, float y) {
    u64 r; asm("mov.b64 %0, {%1, %2};" : "=l"(r) : "f"(x), "f"(y)); return r;
}
__device__ __forceinline__ float2 unpack2(u64 v) {
    float2 f; asm("mov.b64 {%0, %1}, %2;" : "=f"(f.x), "=f"(f.y) : "l"(v)); return f;
}
__device__ __forceinline__ unsigned smem_u32(const void* p) {
    return (unsigned)__cvta_generic_to_shared(p);
}
__device__ __forceinline__ void cp16(unsigned dst, const void* src, bool valid) {
    int sz = valid ? 16 : 0;
    asm volatile("cp.async.ca.shared.global [%0], [%1], 16, %2;" :: "r"(dst), "l"(src), "r"(sz));
}
#define CP_COMMIT() asm volatile("cp.async.commit_group;")
#define CP_WAIT1()  asm volatile("cp.async.wait_group 1;" ::: "memory")
#define CP_WAIT0()  asm volatile("cp.async.wait_group 0;" ::: "memory")

// ---------------- CSR build ----------------
__global__ void k_zero_degi() {
    int i = blockIdx.x * blockDim.x + threadIdx.x;
    if (i < NN) g_degi[i] = 0;
}

__global__ void k_hist(const int* __restrict__ dst) {
    int e = blockIdx.x * blockDim.x + threadIdx.x;
    if (e < NE) atomicAdd(&g_degi[dst[e]], 1);
}

// exclusive scan of g_degi -> g_off, plus cursor copy and degree scalers
__global__ void k_scan() {
    __shared__ int carry;
    __shared__ int warp_sums[32];
    int tid = threadIdx.x;
    if (tid == 0) carry = 0;
    __syncthreads();
    for (int base = 0; base < NN; base += 1024) {
        int i = base + tid;
        int v = (i < NN) ? g_degi[i] : 0;
        int incl = v;
        #pragma unroll
        for (int o = 1; o < 32; o <<= 1) {
            int t = __shfl_up_sync(0xffffffffu, incl, o);
            if ((tid & 31) >= o) incl += t;
        }
        if ((tid & 31) == 31) warp_sums[tid >> 5] = incl;
        __syncthreads();
        if (tid < 32) {
            int s = warp_sums[tid];
            #pragma unroll
            for (int o = 1; o < 32; o <<= 1) {
                int t = __shfl_up_sync(0xffffffffu, s, o);
                if (tid >= o) s += t;
            }
            warp_sums[tid] = s;
        }
        __syncthreads();
        int excl = incl - v + ((tid >= 32) ? warp_sums[(tid >> 5) - 1] : 0);
        if (i < NN) {
            int offv = carry + excl;
            g_off[i] = offv;
            g_cursor[i] = offv;
            float logD = logf((float)v + 1.0f);
            g_amp[i] = logD / 2.5f;
            g_att[i] = (v > 0) ? 2.5f / logD : 0.0f;
        }
        __syncthreads();
        if (tid == 1023) carry += excl + v;
        __syncthreads();
    }
    if (tid == 0) g_off[NN] = NE;
}

__global__ void k_scatter(const int* __restrict__ src, const int* __restrict__ dst) {
    int e = blockIdx.x * blockDim.x + threadIdx.x;
    if (e < NE) {
        int d = dst[e];
        int p = atomicAdd(&g_cursor[d], 1);
        g_csr[p] = src[e];
    }
}

// ---------------- merged message GEMM:  [A|B] = H @ [WM_top | WM_bot] ----------------
// Also zeroes both BN-stats accumulators for this layer.
__global__ __launch_bounds__(256, 2) void gemm_ab(
    const float* __restrict__ H,
    const float* __restrict__ WM,    // 128 x 64 layer slice
    const float* __restrict__ bM)
{
    __shared__ __align__(16) float Xs[2][64][20];
    __shared__ __align__(16) float WAs[2][16][64];
    __shared__ __align__(16) float WBs[2][16][64];

    int tid = threadIdx.x;
    int row0 = blockIdx.y * 64;
    int xr = tid >> 2, xc = (tid & 3) * 4;
    int wr = tid >> 4, wc = (tid & 15) * 4;
    int tx = tid & 15, ty = tid >> 4;

    if (blockIdx.y == 0 && tid < 128) { g_stats[tid] = 0.f; g_stats2[tid] = 0.f; }

    bool xvalid = (row0 + xr) < NN;
    const float* xsrc = H + (size_t)(xvalid ? (row0 + xr) : 0) * 64 + xc;

    u64 accA[4][2] = {}, accB[4][2] = {};

    // prefetch slab 0
    cp16(smem_u32(&Xs[0][xr][xc]), xsrc, xvalid);
    cp16(smem_u32(&WAs[0][wr][wc]), &WM[(size_t)wr * 64 + wc], true);
    cp16(smem_u32(&WBs[0][wr][wc]), &WM[(size_t)(64 + wr) * 64 + wc], true);
    CP_COMMIT();

    for (int sl = 0; sl < 4; sl++) {
        if (sl < 3) {
            int kt = 16 * (sl + 1), s = (sl + 1) & 1;
            cp16(smem_u32(&Xs[s][xr][xc]), xsrc + kt, xvalid);
            cp16(smem_u32(&WAs[s][wr][wc]), &WM[(size_t)(kt + wr) * 64 + wc], true);
            cp16(smem_u32(&WBs[s][wr][wc]), &WM[(size_t)(64 + kt + wr) * 64 + wc], true);
            CP_COMMIT(); CP_WAIT1();
        } else CP_WAIT0();
        __syncthreads();
        int s = sl & 1;
        #pragma unroll
        for (int kk = 0; kk < 16; kk++) {
            ulonglong2 bA = *(const ulonglong2*)&WAs[s][kk][tx * 4];
            ulonglong2 bB = *(const ulonglong2*)&WBs[s][kk][tx * 4];
            #pragma unroll
            for (int i = 0; i < 4; i++) {
                float av = Xs[s][ty * 4 + i][kk];
                u64 ad = pack2(av, av);
                ffma2(accA[i][0], ad, bA.x); ffma2(accA[i][1], ad, bA.y);
                ffma2(accB[i][0], ad, bB.x); ffma2(accB[i][1], ad, bB.y);
            }
        }
        __syncthreads();
    }
    #pragma unroll
    for (int i = 0; i < 4; i++) {
        int r = row0 + ty * 4 + i;
        if (r < NN) {
            #pragma unroll
            for (int j2 = 0; j2 < 2; j2++) {
                int c = tx * 4 + j2 * 2;
                float2 fa = unpack2(accA[i][j2]);
                float2 fb = unpack2(accB[i][j2]);
                fb.x += bM[c]; fb.y += bM[c + 1];
                *(float2*)&g_AB[(size_t)r * 128 + c]      = fa;
                *(float2*)&g_AB[(size_t)r * 128 + 64 + c] = fb;
            }
        }
    }
}

// ---------------- per-node aggregation ----------------
__global__ __launch_bounds__(256) void k_agg() {
    int node = blockIdx.x * (blockDim.x >> 5) + (threadIdx.x >> 5);
    if (node >= NN) return;
    int lane = threadIdx.x & 31;
    int beg = g_off[node], end = g_off[node + 1];

    float sx = 0.f, sy = 0.f, qx = 0.f, qy = 0.f;
    float mxx = -FLT_MAX, mxy = -FLT_MAX, mnx = FLT_MAX, mny = FLT_MAX;
    int e = beg;
    for (; e + 1 < end; e += 2) {
        int s0 = g_csr[e], s1 = g_csr[e + 1];
        float2 a0 = *(const float2*)&g_AB[(size_t)s0 * 128 + 2 * lane];
        float2 a1 = *(const float2*)&g_AB[(size_t)s1 * 128 + 2 * lane];
        sx += a0.x + a1.x; sy += a0.y + a1.y;
        qx += a0.x * a0.x + a1.x * a1.x; qy += a0.y * a0.y + a1.y * a1.y;
        mxx = fmaxf(mxx, fmaxf(a0.x, a1.x)); mxy = fmaxf(mxy, fmaxf(a0.y, a1.y));
        mnx = fminf(mnx, fminf(a0.x, a1.x)); mny = fminf(mny, fminf(a0.y, a1.y));
    }
    if (e < end) {
        int s0 = g_csr[e];
        float2 a0 = *(const float2*)&g_AB[(size_t)s0 * 128 + 2 * lane];
        sx += a0.x; sy += a0.y;
        qx += a0.x * a0.x; qy += a0.y * a0.y;
        mxx = fmaxf(mxx, a0.x); mxy = fmaxf(mxy, a0.y);
        mnx = fminf(mnx, a0.x); mny = fminf(mny, a0.y);
    }
    float degf = (float)(end - beg);
    float denom = fmaxf(degf, 1.0f);
    float2 Bd = *(const float2*)&g_AB[(size_t)node * 128 + 64 + 2 * lane];

    float sumx = sx + degf * Bd.x;
    float sumy = sy + degf * Bd.y;
    float meanx = sumx / denom, meany = sumy / denom;
    float msqx = (qx + 2.f * Bd.x * sx + degf * Bd.x * Bd.x) / denom;
    float msqy = (qy + 2.f * Bd.y * sy + degf * Bd.y * Bd.y) / denom;
    float varx = fmaxf(msqx - meanx * meanx, 0.f);
    float vary = fmaxf(msqy - meany * meany, 0.f);
    float stdx = sqrtf(varx + 1e-30f);
    float stdy = sqrtf(vary + 1e-30f);
    bool has = degf > 0.f;
    float Mx = has ? mxx + Bd.x : 0.f, My = has ? mxy + Bd.y : 0.f;
    float mx_ = has ? mnx + Bd.x : 0.f, my_ = has ? mny + Bd.y : 0.f;

    size_t base = (size_t)node * 384 + 2 * lane;
    *(float2*)&g_AGG[base + 0 * 64] = make_float2(meanx, meany);
    *(float2*)&g_AGG[base + 1 * 64] = make_float2(Mx, My);
    *(float2*)&g_AGG[base + 2 * 64] = make_float2(mx_, my_);
    *(float2*)&g_AGG[base + 3 * 64] = make_float2(stdx, stdy);
    *(float2*)&g_AGG[base + 4 * 64] = make_float2(varx, vary);
    *(float2*)&g_AGG[base + 5 * 64] = make_float2(sumx, sumy);
}

// ---------------- fused update GEMM + BN stats ----------------
// hu = (H@WU0 + AGG@Wid + amp*(AGG@Wamp) + att*(AGG@Watt) + bU) / sqrt(N)
__global__ __launch_bounds__(256, 2) void gemm_hu(
    const float* __restrict__ H,
    const float* __restrict__ WU,   // 1216 x 64 layer slice
    const float* __restrict__ bU)
{
    __shared__ __align__(16) float Xs[2][64][20];
    __shared__ __align__(16) float W0s[2][16][64];
    __shared__ __align__(16) float W1s[2][16][64];
    __shared__ __align__(16) float W2s[2][16][64];
    __shared__ float ssum[64], ssq[64];

    int tid = threadIdx.x;
    int row0 = blockIdx.y * 64;
    int xr = tid >> 2, xc = (tid & 3) * 4;
    int wr = tid >> 4, wc = (tid & 15) * 4;
    int tx = tid & 15, ty = tid >> 4;

    if (tid < 64) { ssum[tid] = 0.f; ssq[tid] = 0.f; }

    bool xvalid = (row0 + xr) < NN;
    const float* xsrcH = H + (size_t)(xvalid ? (row0 + xr) : 0) * 64 + xc;
    const float* xsrcG = g_AGG + (size_t)(xvalid ? (row0 + xr) : 0) * 384 + xc;

    u64 aid[4][2] = {}, aam[4][2] = {}, aat[4][2] = {};

    // phase 1: self features, K=64, W rows [0,64)
    cp16(smem_u32(&Xs[0][xr][xc]), xsrcH, xvalid);
    cp16(smem_u32(&W0s[0][wr][wc]), &WU[(size_t)wr * 64 + wc], true);
    CP_COMMIT();
    for (int sl = 0; sl < 4; sl++) {
        int s1 = (sl + 1) & 1;
        if (sl < 3) {
            int kt = 16 * (sl + 1);
            cp16(smem_u32(&Xs[s1][xr][xc]), xsrcH + kt, xvalid);
            cp16(smem_u32(&W0s[s1][wr][wc]), &WU[(size_t)(kt + wr) * 64 + wc], true);
        } else {
            // chain: prefetch phase-2 slab 0
            cp16(smem_u32(&Xs[s1][xr][xc]), xsrcG, xvalid);
            cp16(smem_u32(&W0s[s1][wr][wc]), &WU[(size_t)(64 + wr) * 64 + wc], true);
            cp16(smem_u32(&W1s[s1][wr][wc]), &WU[(size_t)(448 + wr) * 64 + wc], true);
            cp16(smem_u32(&W2s[s1][wr][wc]), &WU[(size_t)(832 + wr) * 64 + wc], true);
        }
        CP_COMMIT(); CP_WAIT1();
        __syncthreads();
        int s = sl & 1;
        #pragma unroll
        for (int kk = 0; kk < 16; kk++) {
            ulonglong2 b0 = *(const ulonglong2*)&W0s[s][kk][tx * 4];
            #pragma unroll
            for (int i = 0; i < 4; i++) {
                float av = Xs[s][ty * 4 + i][kk];
                u64 ad = pack2(av, av);
                ffma2(aid[i][0], ad, b0.x); ffma2(aid[i][1], ad, b0.y);
            }
        }
        __syncthreads();
    }
    // phase 2: aggregates, K=384, three weight streams
    for (int sl = 0; sl < 24; sl++) {
        if (sl < 23) {
            int kt = 16 * (sl + 1), s1 = (sl + 1) & 1;
            cp16(smem_u32(&Xs[s1][xr][xc]), xsrcG + kt, xvalid);
            cp16(smem_u32(&W0s[s1][wr][wc]), &WU[(size_t)(64 + kt + wr) * 64 + wc], true);
            cp16(smem_u32(&W1s[s1][wr][wc]), &WU[(size_t)(448 + kt + wr) * 64 + wc], true);
            cp16(smem_u32(&W2s[s1][wr][wc]), &WU[(size_t)(832 + kt + wr) * 64 + wc], true);
            CP_COMMIT(); CP_WAIT1();
        } else CP_WAIT0();
        __syncthreads();
        int s = sl & 1;
        #pragma unroll
        for (int kk = 0; kk < 16; kk++) {
            ulonglong2 b0 = *(const ulonglong2*)&W0s[s][kk][tx * 4];
            ulonglong2 b1 = *(const ulonglong2*)&W1s[s][kk][tx * 4];
            ulonglong2 b2 = *(const ulonglong2*)&W2s[s][kk][tx * 4];
            #pragma unroll
            for (int i = 0; i < 4; i++) {
                float av = Xs[s][ty * 4 + i][kk];
                u64 ad = pack2(av, av);
                ffma2(aid[i][0], ad, b0.x); ffma2(aid[i][1], ad, b0.y);
                ffma2(aam[i][0], ad, b1.x); ffma2(aam[i][1], ad, b1.y);
                ffma2(aat[i][0], ad, b2.x); ffma2(aat[i][1], ad, b2.y);
            }
        }
        __syncthreads();
    }
    // epilogue: degree scalers + bias + graph-size norm + BN stats
    #pragma unroll
    for (int i = 0; i < 4; i++) {
        int r = row0 + ty * 4 + i;
        if (r < NN) {
            float amp = g_amp[r], att = g_att[r];
            #pragma unroll
            for (int j2 = 0; j2 < 2; j2++) {
                int c = tx * 4 + j2 * 2;
                float2 fid = unpack2(aid[i][j2]);
                float2 fam = unpack2(aam[i][j2]);
                float2 fat = unpack2(aat[i][j2]);
                float v0 = (fid.x + amp * fam.x + att * fat.x + bU[c])     * INV_SQRT_N;
                float v1 = (fid.y + amp * fam.y + att * fat.y + bU[c + 1]) * INV_SQRT_N;
                *(float2*)&g_HU[(size_t)r * 64 + c] = make_float2(v0, v1);
                atomicAdd(&ssum[c], v0);     atomicAdd(&ssq[c], v0 * v0);
                atomicAdd(&ssum[c + 1], v1); atomicAdd(&ssq[c + 1], v1 * v1);
            }
        }
    }
    __syncthreads();
    if (tid < 64) {
        atomicAdd(&g_stats[tid], ssum[tid]);
        atomicAdd(&g_stats[64 + tid], ssq[tid]);
    }
}

// fold tower BN into Wmix:  hbn@Wmix + bmix == hu@Wp + dp
__global__ void prep_mix(const float* __restrict__ Wmix, const float* __restrict__ bmix,
                         const float* __restrict__ gt, const float* __restrict__ bt) {
    __shared__ float a[64], cc[64];
    int tid = threadIdx.x;
    if (tid < 64) {
        float mu = g_stats[tid] * INV_N;
        float var = g_stats[64 + tid] * INV_N - mu * mu;
        float rstd = rsqrtf(var + 1e-5f);
        float aa = rstd * gt[tid];
        a[tid] = aa;
        cc[tid] = bt[tid] - mu * aa;
    }
    __syncthreads();
    for (int idx = tid; idx < 4096; idx += blockDim.x) {
        int k = idx >> 6;
        g_Wp[idx] = a[k] * Wmix[idx];
    }
    if (tid < 64) {
        float d = bmix[tid];
        for (int k = 0; k < 64; k++) d += cc[k] * Wmix[k * 64 + tid];
        g_dp[tid] = d;
    }
}

// ---------------- mix GEMM: OUT = leaky_relu(HU@Wp + dp) + Hin, + BN stats of OUT ----------------
__global__ __launch_bounds__(256, 2) void gemm_mix(const float* __restrict__ Hin) {
    __shared__ __align__(16) float Xs[2][64][20];
    __shared__ __align__(16) float Ws[2][16][64];
    __shared__ float ssum[64], ssq[64];

    int tid = threadIdx.x;
    int row0 = blockIdx.y * 64;
    int xr = tid >> 2, xc = (tid & 3) * 4;
    int wr = tid >> 4, wc = (tid & 15) * 4;
    int tx = tid & 15, ty = tid >> 4;

    if (tid < 64) { ssum[tid] = 0.f; ssq[tid] = 0.f; }

    bool xvalid = (row0 + xr) < NN;
    const float* xsrc = g_HU + (size_t)(xvalid ? (row0 + xr) : 0) * 64 + xc;

    u64 acc[4][2] = {};

    cp16(smem_u32(&Xs[0][xr][xc]), xsrc, xvalid);
    cp16(smem_u32(&Ws[0][wr][wc]), &g_Wp[(size_t)wr * 64 + wc], true);
    CP_COMMIT();
    for (int sl = 0; sl < 4; sl++) {
        if (sl < 3) {
            int kt = 16 * (sl + 1), s1 = (sl + 1) & 1;
            cp16(smem_u32(&Xs[s1][xr][xc]), xsrc + kt, xvalid);
            cp16(smem_u32(&Ws[s1][wr][wc]), &g_Wp[(size_t)(kt + wr) * 64 + wc], true);
            CP_COMMIT(); CP_WAIT1();
        } else CP_WAIT0();
        __syncthreads();
        int s = sl & 1;
        #pragma unroll
        for (int kk = 0; kk < 16; kk++) {
            ulonglong2 b = *(const ulonglong2*)&Ws[s][kk][tx * 4];
            #pragma unroll
            for (int i = 0; i < 4; i++) {
                float av = Xs[s][ty * 4 + i][kk];
                u64 ad = pack2(av, av);
                ffma2(acc[i][0], ad, b.x); ffma2(acc[i][1], ad, b.y);
            }
        }
        __syncthreads();
    }
    #pragma unroll
    for (int i = 0; i < 4; i++) {
        int r = row0 + ty * 4 + i;
        if (r < NN) {
            #pragma unroll
            for (int j2 = 0; j2 < 2; j2++) {
                int c = tx * 4 + j2 * 2;
                float2 f = unpack2(acc[i][j2]);
                float t0 = f.x + g_dp[c], t1 = f.y + g_dp[c + 1];
                t0 = (t0 > 0.f) ? t0 : 0.01f * t0;
                t1 = (t1 > 0.f) ? t1 : 0.01f * t1;
                float2 hres = *(const float2*)&Hin[(size_t)r * 64 + c];
                float v0 = t0 + hres.x, v1 = t1 + hres.y;
                *(float2*)&g_OUT[(size_t)r * 64 + c] = make_float2(v0, v1);
                atomicAdd(&ssum[c], v0);     atomicAdd(&ssq[c], v0 * v0);
                atomicAdd(&ssum[c + 1], v1); atomicAdd(&ssq[c + 1], v1 * v1);
            }
        }
    }
    __syncthreads();
    if (tid < 64) {
        atomicAdd(&g_stats2[tid], ssum[tid]);
        atomicAdd(&g_stats2[64 + tid], ssq[tid]);
    }
}

// outer wrapper: h_next = relu(bn_o(OUT)) + h
__global__ __launch_bounds__(256) void k_apply(const float* __restrict__ go, const float* __restrict__ bo,
                                               const float* __restrict__ Hin, float* __restrict__ Hout) {
    int idx = blockIdx.x * blockDim.x + threadIdx.x;
    if (idx >= NN * 64) return;
    int c = idx & 63;
    float mu = g_stats2[c] * INV_N;
    float var = g_stats2[64 + c] * INV_N - mu * mu;
    float rstd = rsqrtf(var + 1e-5f);
    float v = (g_OUT[idx] - mu) * rstd * go[c] + bo[c];
    v = fmaxf(v, 0.f);
    Hout[idx] = v + Hin[idx];
}

// ---------------- host ----------------
extern "C" void kernel_launch(void* const* d_in, const int* in_sizes, int n_in,
                              void* d_out, int out_size) {
    const float* node_feat = (const float*)d_in[0];
    const int*   esrc      = (const int*)d_in[2];
    const int*   edst      = (const int*)d_in[3];
    const float* WM        = (const float*)d_in[4];
    const float* bM        = (const float*)d_in[5];
    const float* WU        = (const float*)d_in[6];
    const float* bU        = (const float*)d_in[7];
    const float* gt        = (const float*)d_in[8];
    const float* bt        = (const float*)d_in[9];
    const float* Wmix      = (const float*)d_in[10];
    const float* bmix      = (const float*)d_in[11];
    const float* go        = (const float*)d_in[12];
    const float* bo        = (const float*)d_in[13];
    float* out = (float*)d_out;

    float *pHA, *pHB;
    cudaGetSymbolAddress((void**)&pHA, g_HA);
    cudaGetSymbolAddress((void**)&pHB, g_HB);

    // CSR build (graph static across layers)
    k_zero_degi<<<(NN + 255) / 256, 256>>>();
    k_hist<<<(NE + 255) / 256, 256>>>(edst);
    k_scan<<<1, 1024>>>();
    k_scatter<<<(NE + 255) / 256, 256>>>(esrc, edst);

    dim3 ggrid(1, (NN + 63) / 64);
    for (int l = 0; l < NLAYERS; l++) {
        const float* Hin  = (l == 0) ? node_feat : ((l & 1) ? pHA : pHB);
        float*       Hout = (l == 3) ? out       : ((l & 1) ? pHB : pHA);
        const float* WMl  = WM + (size_t)l * 128 * 64;
        const float* WUl  = WU + (size_t)l * 1216 * 64;

        gemm_ab<<<ggrid, 256>>>(Hin, WMl, bM + l * 64);
        k_agg<<<(NN + 7) / 8, 256>>>();
        gemm_hu<<<ggrid, 256>>>(Hin, WUl, bU + l * 64);
        prep_mix<<<1, 256>>>(Wmix + (size_t)l * 4096, bmix + l * 64, gt + l * 64, bt + l * 64);
        gemm_mix<<<ggrid, 256>>>(Hin);
        k_apply<<<(NN * 64 + 255) / 256, 256>>>(go + l * 64, bo + l * 64, Hin, Hout);
    }
}